// round 12
// baseline (speedup 1.0000x reference)
#include <cuda_runtime.h>
#include <cstdint>

#define BATCH      16384
#define FIELD_DIM  100000
#define THREADS    256
#define WARPS      8
#define RPW        4
#define DEPTH      2
#define NBLOCKS    (BATCH / (WARPS * RPW))   // 512
#define PAD        66

// ---- dynamic smem layout (bytes) ----
#define SM_W1    0                                   // 32*66*4 = 8448
#define SM_W2    8448                                // 16*66*4 = 4224
#define SM_BIAS  12672                               // 64*4    = 256
#define SM_SS    12928                               // 8*48*4  = 1536
#define SM_MBAR  14464                               // 8*2*8   = 128
#define SM_BUF   14592                               // 8*2*3712 = 59392
#define ROWBUF   3712
#define SMEM_TOTAL (SM_BUF + WARPS * DEPTH * ROWBUF) // 73984

__device__ __forceinline__ uint32_t smem_u32(const void* p) {
    uint32_t a;
    asm("{ .reg .u64 t; cvta.to.shared.u64 t, %1; cvt.u32.u64 %0, t; }" : "=r"(a) : "l"(p));
    return a;
}
__device__ __forceinline__ void bulk_ld(uint32_t dst, const void* src,
                                        uint32_t bytes, uint32_t mbar) {
    asm volatile(
        "cp.async.bulk.shared::cluster.global.mbarrier::complete_tx::bytes "
        "[%0], [%1], %2, [%3];"
        :: "r"(dst), "l"(src), "r"(bytes), "r"(mbar) : "memory");
}
__device__ __forceinline__ void mbar_wait(uint32_t mbar, int parity) {
    asm volatile(
        "{\n\t.reg .pred P;\n\t"
        "WL%=:\n\t"
        "mbarrier.try_wait.parity.acquire.cta.shared::cta.b64 P, [%0], %1, 0x989680;\n\t"
        "@!P bra WL%=;\n\t}"
        :: "r"(mbar), "r"(parity) : "memory");
}

__global__ __launch_bounds__(THREADS) void pipe_fused_kernel(
    const int*   __restrict__ x,
    const float* __restrict__ t0,   // [800000, 64]
    const float* __restrict__ t1,   // [800000, 32]
    const float* __restrict__ t2,   // [1000000, 16]
    const float* __restrict__ W1, const float* __restrict__ b1,
    const float* __restrict__ W2, const float* __restrict__ b2,
    float*       __restrict__ out)
{
    extern __shared__ char smem[];
    float* sW1f   = (float*)(smem + SM_W1);
    float* sW2f   = (float*)(smem + SM_W2);
    float* sBiasF = (float*)(smem + SM_BIAS);

    const int tid  = threadIdx.x;
    const int warp = tid >> 5;
    const int lane = tid & 31;
    const unsigned FULL = 0xffffffffu;
    const uint32_t sb = smem_u32(smem);
    const uint32_t mb = sb + SM_MBAR + warp * DEPTH * 8;   // 2 mbarriers per warp
    float* sS = (float*)(smem + SM_SS) + warp * 48;

    // ---- mbarrier init ----
    if (lane == 0) {
        asm volatile("mbarrier.init.shared.b64 [%0], %1;" :: "r"(mb),     "r"(1) : "memory");
        asm volatile("mbarrier.init.shared.b64 [%0], %1;" :: "r"(mb + 8), "r"(1) : "memory");
    }

    // ---- stage W: coalesced LDG, transposed STS (pad-66) ----
    #pragma unroll
    for (int i = tid; i < 64 * 32; i += THREADS) {
        int o = i >> 5, k = i & 31;
        sW1f[k * PAD + o] = W1[i];
    }
    #pragma unroll
    for (int i = tid; i < 64 * 16; i += THREADS) {
        int o = i >> 4, k = i & 15;
        sW2f[k * PAD + o] = W2[i];
    }
    if (tid < 64) sBiasF[tid] = 8.f * b1[tid] + 10.f * b2[tid];

    asm volatile("fence.proxy.async.shared::cta;" ::: "memory");
    __syncthreads();

    const int row0 = (blockIdx.x * WARPS + warp) * RPW;
    const uint32_t bufbase = sb + SM_BUF + warp * DEPTH * ROWBUF;

    // per-lane own-field indices for all RPW rows (no shuffles needed at issue)
    int idx[RPW];
    #pragma unroll
    for (int i = 0; i < RPW; i++)
        idx[i] = (lane < 26) ? x[(row0 + i) * 26 + lane] : 0;

    // ---- issue one row's 26 bulk copies into buffer s (lane owns its field) ----
    auto issue_row = [&](int myidx, int s) {
        const uint32_t buf  = bufbase + s * ROWBUF;
        const uint32_t mbar = mb + s * 8;
        if (lane == 0)
            asm volatile("mbarrier.arrive.expect_tx.shared.b64 _, [%0], %1;"
                         :: "r"(mbar), "r"(ROWBUF) : "memory");
        __syncwarp();
        if (lane < 8) {
            unsigned f = lane;
            bulk_ld(buf + f * 256, t0 + ((unsigned)myidx + f * FIELD_DIM) * 64u, 256, mbar);
        } else if (lane < 16) {
            unsigned f = lane - 8;
            bulk_ld(buf + 2048 + f * 128, t1 + ((unsigned)myidx + f * FIELD_DIM) * 32u, 128, mbar);
        } else if (lane < 26) {
            unsigned f = lane - 16;
            bulk_ld(buf + 3072 + f * 64, t2 + ((unsigned)myidx + f * FIELD_DIM) * 16u, 64, mbar);
        }
    };

    const float2 bias = *(const float2*)&sBiasF[2 * lane];
    const int half = lane >> 4;
    const int l16  = lane & 15;

    // ---- fill the pipeline: rows 0 and 1 in flight ----
    issue_row(idx[0], 0);
    issue_row(idx[1], 1);

    // ---- steady-state: wait -> reduce+project+store -> reissue ----
    #pragma unroll
    for (int i = 0; i < RPW; i++) {
        const int s = i & 1;
        mbar_wait(mb + s * 8, i >> 1);          // parities: 0,0,1,1

        const char* bp = smem + SM_BUF + (warp * DEPTH + s) * ROWBUF;

        float2 acc = bias;
        #pragma unroll
        for (int f = 0; f < 8; f++) {
            float2 a = *(const float2*)(bp + f * 256 + lane * 8);
            acc.x += a.x; acc.y += a.y;
        }
        float s1 = 0.f;
        #pragma unroll
        for (int f = 0; f < 8; f++)
            s1 += *(const float*)(bp + 2048 + f * 128 + lane * 4);
        float s2 = 0.f;
        #pragma unroll
        for (int p = 0; p < 5; p++) {
            int f = 2 * p + half;
            s2 += *(const float*)(bp + 3072 + f * 64 + l16 * 4);
        }
        s2 += __shfl_xor_sync(FULL, s2, 16);

        // buffer fully read -> safe to reissue into this slot
        __syncwarp();
        if (i + DEPTH < RPW) issue_row(idx[i + DEPTH], s);

        // stage block-sums for uniform broadcast (sS reuse guarded by syncwarps)
        sS[lane] = s1;
        if (lane < 16) sS[32 + lane] = s2;
        __syncwarp();

        #pragma unroll
        for (int k4 = 0; k4 < 12; k4++) {
            float4 sv = *(const float4*)&sS[k4 * 4];
            #pragma unroll
            for (int j = 0; j < 4; j++) {
                const int k = k4 * 4 + j;
                float2 w;
                if (k < 32) w = *(const float2*)&sW1f[k * PAD + 2 * lane];
                else        w = *(const float2*)&sW2f[(k - 32) * PAD + 2 * lane];
                float v = (j == 0) ? sv.x : (j == 1) ? sv.y : (j == 2) ? sv.z : sv.w;
                acc.x += w.x * v;
                acc.y += w.y * v;
            }
        }
        __syncwarp();   // all sS reads done before next iteration overwrites

        ((float2*)(out + (long long)(row0 + i) * 64))[lane] = acc;
    }
}

extern "C" void kernel_launch(void* const* d_in, const int* in_sizes, int n_in,
                              void* d_out, int out_size)
{
    const int*   x  = (const int*)  d_in[0];
    const float* t0 = (const float*)d_in[1];
    const float* t1 = (const float*)d_in[2];
    const float* t2 = (const float*)d_in[3];
    const float* W1 = (const float*)d_in[4];
    const float* b1 = (const float*)d_in[5];
    const float* W2 = (const float*)d_in[6];
    const float* b2 = (const float*)d_in[7];
    float* out = (float*)d_out;

    static bool attr_set = false;
    if (!attr_set) {
        cudaFuncSetAttribute(pipe_fused_kernel,
                             cudaFuncAttributeMaxDynamicSharedMemorySize, SMEM_TOTAL);
        attr_set = true;
    }
    pipe_fused_kernel<<<NBLOCKS, THREADS, SMEM_TOTAL>>>(
        x, t0, t1, t2, W1, b1, W2, b2, out);
}

// round 13
// speedup vs baseline: 1.3529x; 1.3529x over previous
#include <cuda_runtime.h>
#include <cstdint>

#define BATCH      16384
#define FIELD_DIM  100000
#define THREADS    256
#define WARPS      8
#define NBLOCKS    (BATCH / (WARPS * 2))   // 1024, 2 rows per warp
#define WPAD       68                      // floats per k-row of transposed W

__global__ __launch_bounds__(THREADS, 3) void fused_kernel(
    const int*   __restrict__ x,    // [B, 26]
    const float* __restrict__ t0,   // [800000, 64]
    const float* __restrict__ t1,   // [800000, 32]
    const float* __restrict__ t2,   // [1000000, 16]
    const float* __restrict__ W1,   // [64, 32]
    const float* __restrict__ b1,   // [64]
    const float* __restrict__ W2,   // [64, 16]
    const float* __restrict__ b2,   // [64]
    float*       __restrict__ out)  // [B, 64]
{
    // sWf[k*WPAD + o] = W[o][k]  (k<32: W1, k>=32: W2[k-32]); 16B-aligned quads
    __shared__ float sWf[48 * WPAD];
    __shared__ float sB[64];
    __shared__ float sS[WARPS][2][48];

    const int tid  = threadIdx.x;
    const int warp = tid >> 5;
    const int lane = tid & 31;
    const unsigned FULL = 0xffffffffu;

    // ---- stage W: coalesced LDG, transposed STS ----
    #pragma unroll
    for (int i = tid; i < 64 * 32; i += THREADS) {
        int o = i >> 5, k = i & 31;
        sWf[k * WPAD + o] = W1[i];
    }
    #pragma unroll
    for (int i = tid; i < 64 * 16; i += THREADS) {
        int o = i >> 4, k = i & 15;
        sWf[(32 + k) * WPAD + o] = W2[i];
    }
    if (tid < 64) sB[tid] = 8.f * b1[tid] + 10.f * b2[tid];
    __syncthreads();

    const int row0 = (blockIdx.x * WARPS + warp) * 2;

    int i0 = 0, i1 = 0;
    if (lane < 26) {
        i0 = x[(row0 + 0) * 26 + lane];
        i1 = x[(row0 + 1) * 26 + lane];
    }

    // ===== all gathers as 512B warp-loads (LDG.128, rows packed) =====

    // block 0: t0 rows 256B -> 2 rows per load. lanes 0-15 row a, 16-31 row b.
    float4 v0[8];
    #pragma unroll
    for (int f = 0; f < 8; f++) {
        unsigned ia = (unsigned)__shfl_sync(FULL, i0, f);
        unsigned ib = (unsigned)__shfl_sync(FULL, i1, f);
        unsigned sel = (lane < 16) ? ia : ib;
        v0[f] = __ldg(&((const float4*)t0)[(sel + (unsigned)(f * FIELD_DIM)) * 16u + (lane & 15)]);
    }

    // block 1: t1 rows 128B -> 4 row-instances per load.
    // g = lane>>3: 0:(a,f even) 1:(b,f even) 2:(a,f odd) 3:(b,f odd)
    const int g1 = lane >> 3;
    float4 v1[4];
    #pragma unroll
    for (int fp = 0; fp < 4; fp++) {
        int fld = 2 * fp + (g1 >> 1);
        unsigned ia = (unsigned)__shfl_sync(FULL, i0, 8 + fld);
        unsigned ib = (unsigned)__shfl_sync(FULL, i1, 8 + fld);
        unsigned sel = (g1 & 1) ? ib : ia;
        v1[fp] = __ldg(&((const float4*)t1)[(sel + (unsigned)(fld * FIELD_DIM)) * 8u + (lane & 7)]);
    }

    // block 2: t2 rows 64B -> 8 row-instances per load. id = 8j+g2; row=id&1, fld=id>>1.
    const int g2 = lane >> 2;
    float4 v2[3];
    #pragma unroll
    for (int j = 0; j < 3; j++) {
        int id  = 8 * j + g2;           // 0..23, valid < 20
        int fld = id >> 1;
        int fsrc = 16 + ((fld < 10) ? fld : 9);
        unsigned ia = (unsigned)__shfl_sync(FULL, i0, fsrc);
        unsigned ib = (unsigned)__shfl_sync(FULL, i1, fsrc);
        unsigned sel = (id & 1) ? ib : ia;
        if (id < 20)
            v2[j] = __ldg(&((const float4*)t2)[(sel + (unsigned)(fld * FIELD_DIM)) * 4u + (lane & 3)]);
        else
            v2[j] = make_float4(0.f, 0.f, 0.f, 0.f);
    }

    // ===== reductions =====

    // block0: per-lane 4 cols of its row
    float4 acc = *(const float4*)&sB[(lane & 15) * 4];
    #pragma unroll
    for (int f = 0; f < 8; f++) {
        acc.x += v0[f].x; acc.y += v0[f].y; acc.z += v0[f].z; acc.w += v0[f].w;
    }

    // block1: sum over field-pairs, then fold g^2 (xor16) -> row-pure quads
    float4 s1 = v1[0];
    s1.x += v1[1].x + v1[2].x + v1[3].x;
    s1.y += v1[1].y + v1[2].y + v1[3].y;
    s1.z += v1[1].z + v1[2].z + v1[3].z;
    s1.w += v1[1].w + v1[2].w + v1[3].w;
    s1.x += __shfl_xor_sync(FULL, s1.x, 16);
    s1.y += __shfl_xor_sync(FULL, s1.y, 16);
    s1.z += __shfl_xor_sync(FULL, s1.z, 16);
    s1.w += __shfl_xor_sync(FULL, s1.w, 16);
    // now: lanes 0-7 hold row-a s1 quad (lane&7); lanes 8-15 row-b

    // block2: sum over j, fold g^2 (xor8) and g^4 (xor16) -> row-pure quads
    float4 s2 = v2[0];
    s2.x += v2[1].x + v2[2].x;  s2.y += v2[1].y + v2[2].y;
    s2.z += v2[1].z + v2[2].z;  s2.w += v2[1].w + v2[2].w;
    #pragma unroll
    for (int m = 8; m <= 16; m <<= 1) {
        s2.x += __shfl_xor_sync(FULL, s2.x, m);
        s2.y += __shfl_xor_sync(FULL, s2.y, m);
        s2.z += __shfl_xor_sync(FULL, s2.z, m);
        s2.w += __shfl_xor_sync(FULL, s2.w, m);
    }
    // now: lanes with g2 even hold row-a s2 quad (lane&3); g2 odd row-b

    // ---- stage block-sums (row-major: sS[warp][row][48]) ----
    if (lane < 8)        *(float4*)&sS[warp][0][(lane & 7) * 4] = s1;   // row a s1
    else if (lane < 16)  *(float4*)&sS[warp][1][(lane & 7) * 4] = s1;   // row b s1
    if (g2 == 0)         *(float4*)&sS[warp][0][32 + (lane & 3) * 4] = s2;  // row a s2
    else if (g2 == 1)    *(float4*)&sS[warp][1][32 + (lane & 3) * 4] = s2;  // row b s2
    __syncwarp();

    // ===== projection: lane owns 4 cols of its row =====
    const float* sR = sS[warp][lane >> 4];
    const int q = lane & 15;

    #pragma unroll
    for (int k4 = 0; k4 < 12; k4++) {
        float4 sv = *(const float4*)&sR[k4 * 4];   // 2 addrs/warp -> broadcast
        #pragma unroll
        for (int j = 0; j < 4; j++) {
            const int k = k4 * 4 + j;
            float4 w = *(const float4*)&sWf[k * WPAD + 4 * q];
            float v = (j == 0) ? sv.x : (j == 1) ? sv.y : (j == 2) ? sv.z : sv.w;
            acc.x += w.x * v; acc.y += w.y * v;
            acc.z += w.z * v; acc.w += w.w * v;
        }
    }

    // ---- store: lanes 0-15 write row a (256B), 16-31 row b ----
    const int myrow = row0 + (lane >> 4);
    ((float4*)(out + (long long)myrow * 64))[q] = acc;
}

extern "C" void kernel_launch(void* const* d_in, const int* in_sizes, int n_in,
                              void* d_out, int out_size)
{
    const int*   x  = (const int*)  d_in[0];
    const float* t0 = (const float*)d_in[1];
    const float* t1 = (const float*)d_in[2];
    const float* t2 = (const float*)d_in[3];
    const float* W1 = (const float*)d_in[4];
    const float* b1 = (const float*)d_in[5];
    const float* W2 = (const float*)d_in[6];
    const float* b2 = (const float*)d_in[7];
    float* out = (float*)d_out;

    fused_kernel<<<NBLOCKS, THREADS>>>(x, t0, t1, t2, W1, b1, W2, b2, out);
}

// round 15
// speedup vs baseline: 1.5400x; 1.1382x over previous
#include <cuda_runtime.h>
#include <cstdint>

#define BATCH      16384
#define FIELD_DIM  100000
#define THREADS    256
#define WARPS      8
#define RPW        2
#define NBLOCKS    (BATCH / (WARPS * RPW))   // 1024
#define PAD        66

__device__ __forceinline__ uint64_t mk_evict_last_policy() {
    uint64_t pol;
    asm("createpolicy.fractional.L2::evict_last.b64 %0, 1.0;" : "=l"(pol));
    return pol;
}
__device__ __forceinline__ float2 ldg_el_v2(const float* p, uint64_t pol) {
    float2 r;
    asm volatile("ld.global.nc.L2::cache_hint.v2.f32 {%0, %1}, [%2], %3;"
                 : "=f"(r.x), "=f"(r.y) : "l"(p), "l"(pol));
    return r;
}
__device__ __forceinline__ float ldg_el(const float* p, uint64_t pol) {
    float r;
    asm volatile("ld.global.nc.L2::cache_hint.f32 %0, [%1], %2;"
                 : "=f"(r) : "l"(p), "l"(pol));
    return r;
}

__global__ __launch_bounds__(THREADS, 4) void fused_kernel(
    const int*   __restrict__ x,    // [B, 26]
    const float* __restrict__ t0,   // [800000, 64]
    const float* __restrict__ t1,   // [800000, 32]
    const float* __restrict__ t2,   // [1000000, 16]
    const float* __restrict__ W1,   // [64, 32]
    const float* __restrict__ b1,   // [64]
    const float* __restrict__ W2,   // [64, 16]
    const float* __restrict__ b2,   // [64]
    float*       __restrict__ out)  // [B, 64]
{
    // Transposed W, pad-66 rows: sW1f[k*PAD + o] = W1[o][k]
    __shared__ float sW1f[32 * PAD];
    __shared__ float sW2f[16 * PAD];
    __shared__ float sBiasF[64];
    __shared__ float sS[WARPS][RPW][48];

    const int tid  = threadIdx.x;
    const int warp = tid >> 5;
    const int lane = tid & 31;
    const unsigned FULL = 0xffffffffu;
    const uint64_t pol = mk_evict_last_policy();

    // ---- stage W: coalesced LDG, transposed STS (2-way conflicts max) ----
    #pragma unroll
    for (int i = tid; i < 64 * 32; i += THREADS) {
        int o = i >> 5, k = i & 31;
        sW1f[k * PAD + o] = W1[i];
    }
    #pragma unroll
    for (int i = tid; i < 64 * 16; i += THREADS) {
        int o = i >> 4, k = i & 15;
        sW2f[k * PAD + o] = W2[i];
    }
    if (tid < 64) sBiasF[tid] = 8.f * b1[tid] + 10.f * b2[tid];
    __syncthreads();

    const int row0 = (blockIdx.x * WARPS + warp) * RPW;

    // ---- load indices for both rows ----
    int i0 = 0, i1 = 0;
    if (lane < 26) {
        i0 = x[(row0 + 0) * 26 + lane];
        i1 = x[(row0 + 1) * 26 + lane];
    }

    // ---- issue ALL gathers for both rows back-to-back (max MLP),
    //      evict_last policy so table lines persist in L2 across replays ----
    float2 v0a[8], v0b[8];
    #pragma unroll
    for (int f = 0; f < 8; f++) {
        unsigned ia = (unsigned)__shfl_sync(FULL, i0, f) + (unsigned)(f * FIELD_DIM);
        unsigned ib = (unsigned)__shfl_sync(FULL, i1, f) + (unsigned)(f * FIELD_DIM);
        v0a[f] = ldg_el_v2(t0 + (ia * 64u + lane * 2u), pol);
        v0b[f] = ldg_el_v2(t0 + (ib * 64u + lane * 2u), pol);
    }
    float v1a[8], v1b[8];
    #pragma unroll
    for (int f = 0; f < 8; f++) {
        unsigned ia = (unsigned)__shfl_sync(FULL, i0, 8 + f) + (unsigned)(f * FIELD_DIM);
        unsigned ib = (unsigned)__shfl_sync(FULL, i1, 8 + f) + (unsigned)(f * FIELD_DIM);
        v1a[f] = ldg_el(t1 + (ia * 32u + lane), pol);
        v1b[f] = ldg_el(t1 + (ib * 32u + lane), pol);
    }
    const int half = lane >> 4;
    const int l16  = lane & 15;
    float v2a[5], v2b[5];
    #pragma unroll
    for (int p = 0; p < 5; p++) {
        int f = 2 * p + half;
        unsigned ia = (unsigned)__shfl_sync(FULL, i0, 16 + f) + (unsigned)f * FIELD_DIM;
        unsigned ib = (unsigned)__shfl_sync(FULL, i1, 16 + f) + (unsigned)f * FIELD_DIM;
        v2a[p] = ldg_el(t2 + (ia * 16u + l16), pol);
        v2b[p] = ldg_el(t2 + (ib * 16u + l16), pol);
    }

    // ---- reductions ----
    const float2 bias = *(const float2*)&sBiasF[2 * lane];
    float2 acc0 = bias, acc1 = bias;
    #pragma unroll
    for (int f = 0; f < 8; f++) {
        acc0.x += v0a[f].x; acc0.y += v0a[f].y;
        acc1.x += v0b[f].x; acc1.y += v0b[f].y;
    }

    float s1a = 0.f, s1b = 0.f;
    #pragma unroll
    for (int f = 0; f < 8; f++) { s1a += v1a[f]; s1b += v1b[f]; }

    float s2a = 0.f, s2b = 0.f;
    #pragma unroll
    for (int p = 0; p < 5; p++) { s2a += v2a[p]; s2b += v2b[p]; }
    s2a += __shfl_xor_sync(FULL, s2a, 16);
    s2b += __shfl_xor_sync(FULL, s2b, 16);

    // ---- stage block-sums for uniform broadcast ----
    sS[warp][0][lane] = s1a;
    sS[warp][1][lane] = s1b;
    if (lane < 16) {
        sS[warp][0][32 + lane] = s2a;
        sS[warp][1][32 + lane] = s2b;
    }
    __syncwarp();

    // ---- projection: 48 k-steps, W-LDS amortized over 2 rows ----
    #pragma unroll
    for (int k4 = 0; k4 < 12; k4++) {
        float4 sa = *(const float4*)&sS[warp][0][k4 * 4];   // uniform bcast
        float4 sb = *(const float4*)&sS[warp][1][k4 * 4];
        #pragma unroll
        for (int j = 0; j < 4; j++) {
            const int k = k4 * 4 + j;                       // compile-time
            float2 w;
            if (k < 32) w = *(const float2*)&sW1f[k * PAD + 2 * lane];
            else        w = *(const float2*)&sW2f[(k - 32) * PAD + 2 * lane];
            float va = (j == 0) ? sa.x : (j == 1) ? sa.y : (j == 2) ? sa.z : sa.w;
            float vb = (j == 0) ? sb.x : (j == 1) ? sb.y : (j == 2) ? sb.z : sb.w;
            acc0.x += w.x * va; acc0.y += w.y * va;
            acc1.x += w.x * vb; acc1.y += w.y * vb;
        }
    }

    // ---- single coalesced store per row ----
    ((float2*)(out + (long long)(row0 + 0) * 64))[lane] = acc0;
    ((float2*)(out + (long long)(row0 + 1) * 64))[lane] = acc1;
}

extern "C" void kernel_launch(void* const* d_in, const int* in_sizes, int n_in,
                              void* d_out, int out_size)
{
    const int*   x  = (const int*)  d_in[0];
    const float* t0 = (const float*)d_in[1];
    const float* t1 = (const float*)d_in[2];
    const float* t2 = (const float*)d_in[3];
    const float* W1 = (const float*)d_in[4];
    const float* b1 = (const float*)d_in[5];
    const float* W2 = (const float*)d_in[6];
    const float* b2 = (const float*)d_in[7];
    float* out = (float*)d_out;

    fused_kernel<<<NBLOCKS, THREADS>>>(x, t0, t1, t2, W1, b1, W2, b2, out);
}